// round 15
// baseline (speedup 1.0000x reference)
#include <cuda_runtime.h>
#include <cuda_bf16.h>
#include <cstdint>
#include <math.h>

#define TOKENS 4096
#define DMODEL 4096
#define SEQ    2048
#define NBATCH 2
#define NHEADS 32
#define DHEAD  128
#define DFF    11008
#define QKVDIM (3*DMODEL)

// ---------------- scratch (device globals: allocation-free) ----------------
__device__ float g_qkv    [(size_t)TOKENS * QKVDIM];
__device__ float g_hidden [(size_t)TOKENS * DMODEL];
__device__ __nv_bfloat16 g_ahi[(size_t)TOKENS * DFF];
__device__ __nv_bfloat16 g_alo[(size_t)TOKENS * DFF];
__device__ __nv_bfloat16 g_bhi[(size_t)(2*DFF) * DMODEL];
__device__ __nv_bfloat16 g_blo[(size_t)(2*DFF) * DMODEL];

// ================= helpers =================
__device__ __forceinline__ uint32_t smem_u32(const void* p) {
    uint32_t a;
    asm("{ .reg .u64 t; cvta.to.shared.u64 t, %1; cvt.u32.u64 %0, t; }" : "=r"(a) : "l"(p));
    return a;
}
#define CP_ASYNC16(s, g) asm volatile("cp.async.cg.shared.global [%0], [%1], 16;" :: "r"(s), "l"(g))
#define CP_COMMIT() asm volatile("cp.async.commit_group;" ::: "memory")
#define CP_WAIT0()  asm volatile("cp.async.wait_group 0;" ::: "memory")
#define CP_WAIT1()  asm volatile("cp.async.wait_group 1;" ::: "memory")

__device__ __forceinline__ void ldsm_x4(uint32_t* r, uint32_t addr) {
    asm volatile("ldmatrix.sync.aligned.m8n8.x4.shared.b16 {%0,%1,%2,%3}, [%4];"
        : "=r"(r[0]), "=r"(r[1]), "=r"(r[2]), "=r"(r[3]) : "r"(addr));
}
__device__ __forceinline__ void ldsm_x2(uint32_t* r, uint32_t addr) {
    asm volatile("ldmatrix.sync.aligned.m8n8.x2.shared.b16 {%0,%1}, [%2];"
        : "=r"(r[0]), "=r"(r[1]) : "r"(addr));
}
__device__ __forceinline__ void mma16816(float* c, const uint32_t* a, const uint32_t* b) {
    asm volatile(
        "mma.sync.aligned.m16n8k16.row.col.f32.bf16.bf16.f32 "
        "{%0,%1,%2,%3}, {%4,%5,%6,%7}, {%8,%9}, {%0,%1,%2,%3};"
        : "+f"(c[0]), "+f"(c[1]), "+f"(c[2]), "+f"(c[3])
        : "r"(a[0]), "r"(a[1]), "r"(a[2]), "r"(a[3]), "r"(b[0]), "r"(b[1]));
}
__device__ __forceinline__ void split_bf16(float v, __nv_bfloat16& h, __nv_bfloat16& l) {
    h = __float2bfloat16(v);
    l = __float2bfloat16(v - __bfloat162float(h));
}

// ================= HMMA GEMM (bf16 split, fp32 acc) =================
// Tile 128x256x32, 512 thr (16 warps: 4m x 4n), warp tile 32x64, 1 CTA/SM (16 warps/SM).
// Same double-buffer / two-barrier loop as R8; 25% lower smem-fill bytes per FLOP.
// MODE 0: C = A@B (+bias)(+res) fp32.  MODE 1: interleaved gate/up -> mid = silu(g)*u, bf16 hi/lo.
#define OFF_AH 0
#define OFF_AL 10240
#define OFF_BH 20480
#define OFF_BL 40960
#define BUFB   61440
#define GSMEM  (2*BUFB)
#define RASTG  8

__device__ __forceinline__ void g2s_a(uint32_t dst, const __nv_bfloat16* src,
                                      int row0, int K, int k0, int tid)
{
    int r = tid >> 2, c8 = (tid & 3) << 3;           // 128 rows x 4 segs = 512
    CP_ASYNC16(dst + r * 80 + (c8 << 1),
               (const char*)(src + (size_t)(row0 + r) * K + k0 + c8));
}
__device__ __forceinline__ void g2s_b(uint32_t dst, const __nv_bfloat16* src,
                                      int row0, int K, int k0, int tid)
{
    #pragma unroll
    for (int it = 0; it < 2; it++) {                 // 256 rows x 4 segs = 1024
        int idx = tid + it * 512;
        int r = idx >> 2, c8 = (idx & 3) << 3;
        CP_ASYNC16(dst + r * 80 + (c8 << 1),
                   (const char*)(src + (size_t)(row0 + r) * K + k0 + c8));
    }
}

template <int MODE>
__global__ __launch_bounds__(512, 1) void mma_gemm_kernel(
    int M, int N, int K,
    const __nv_bfloat16* __restrict__ Ah, const __nv_bfloat16* __restrict__ Al,
    const __nv_bfloat16* __restrict__ Bh, const __nv_bfloat16* __restrict__ Bl,
    float* __restrict__ C, const float* __restrict__ bias, const float* __restrict__ res,
    __nv_bfloat16* __restrict__ mh, __nv_bfloat16* __restrict__ ml)
{
    extern __shared__ char smem[];
    const uint32_t sb = smem_u32(smem);
    const int tid = threadIdx.x;
    const int wid = tid >> 5, lane = tid & 31;
    const int g = lane >> 2, tig = lane & 3;
    const int wm = wid & 3, wn = wid >> 2;           // 4m x 4n

    const int NB = N >> 8, MB = M >> 7;
    const int bid = blockIdx.x;
    const int per_group = RASTG * NB;
    const int group = bid / per_group;
    const int first_m = group * RASTG;
    const int gsz = min(RASTG, MB - first_m);
    const int rem = bid - group * per_group;
    const int bm = (first_m + rem % gsz) << 7;
    const int bn = (rem / gsz) << 8;

    const int rsel = lane & 15;
    const int kh   = lane >> 4;
    const int brow = lane & 7;
    const int bkh  = (lane >> 3) & 1;

    float acc[2][8][4];
    #pragma unroll
    for (int mt = 0; mt < 2; mt++)
        #pragma unroll
        for (int nt = 0; nt < 8; nt++)
            #pragma unroll
            for (int e = 0; e < 4; e++) acc[mt][nt][e] = 0.f;

    const int NC = K >> 5;
    g2s_a(sb + OFF_AH, Ah, bm, K, 0, tid);
    g2s_a(sb + OFF_AL, Al, bm, K, 0, tid);
    g2s_b(sb + OFF_BH, Bh, bn, K, 0, tid);
    g2s_b(sb + OFF_BL, Bl, bn, K, 0, tid);
    CP_COMMIT();

    for (int ck = 0; ck < NC; ck++) {
        if (ck + 1 < NC) {
            const uint32_t nb = sb + (uint32_t)((ck + 1) & 1) * BUFB;
            const int k1 = (ck + 1) << 5;
            g2s_a(nb + OFF_AH, Ah, bm, K, k1, tid);
            g2s_a(nb + OFF_AL, Al, bm, K, k1, tid);
            g2s_b(nb + OFF_BH, Bh, bn, K, k1, tid);
            g2s_b(nb + OFF_BL, Bl, bn, K, k1, tid);
            CP_COMMIT();
            CP_WAIT1();
        } else {
            CP_WAIT0();
        }
        __syncthreads();

        const uint32_t bb = sb + (uint32_t)(ck & 1) * BUFB;
        #pragma unroll
        for (int ks = 0; ks < 2; ks++) {
            uint32_t ahf[2][4], alf[2][4];
            #pragma unroll
            for (int mt = 0; mt < 2; mt++) {
                const uint32_t ao = (uint32_t)((wm * 32 + mt * 16 + rsel) * 80
                                               + ((ks << 4) + kh * 8) * 2);
                ldsm_x4(ahf[mt], bb + OFF_AH + ao);
                ldsm_x4(alf[mt], bb + OFF_AL + ao);
            }
            #pragma unroll
            for (int nt = 0; nt < 8; nt++) {
                const uint32_t bo = (uint32_t)((wn * 64 + nt * 8 + brow) * 80
                                               + ((ks << 4) + bkh * 8) * 2);
                uint32_t bh[2], bl[2];
                ldsm_x2(bh, bb + OFF_BH + bo);
                ldsm_x2(bl, bb + OFF_BL + bo);
                #pragma unroll
                for (int mt = 0; mt < 2; mt++) {
                    mma16816(acc[mt][nt], ahf[mt], bh);
                    mma16816(acc[mt][nt], alf[mt], bh);
                    mma16816(acc[mt][nt], ahf[mt], bl);
                }
            }
        }
        __syncthreads();
    }

    if (MODE == 0) {
        #pragma unroll
        for (int nt = 0; nt < 8; nt++) {
            const int c = bn + wn * 64 + nt * 8 + (tig << 1);
            float bx = 0.f, by = 0.f;
            if (bias) { bx = bias[c]; by = bias[c + 1]; }
            #pragma unroll
            for (int mt = 0; mt < 2; mt++) {
                const int r0 = bm + wm * 32 + mt * 16 + g;
                float2 v0 = make_float2(acc[mt][nt][0] + bx, acc[mt][nt][1] + by);
                float2 v1 = make_float2(acc[mt][nt][2] + bx, acc[mt][nt][3] + by);
                size_t g0 = (size_t)r0 * N + c;
                size_t g1 = (size_t)(r0 + 8) * N + c;
                if (res) {
                    float2 r0v = *(const float2*)(res + g0);
                    float2 r1v = *(const float2*)(res + g1);
                    v0.x += r0v.x; v0.y += r0v.y; v1.x += r1v.x; v1.y += r1v.y;
                }
                *(float2*)(C + g0) = v0;
                *(float2*)(C + g1) = v1;
            }
        }
    } else {
        const int NW = N >> 1;   // mid width = DFF
        #pragma unroll
        for (int nt = 0; nt < 8; nt++) {
            const int c = bn + wn * 64 + nt * 8 + (tig << 1);
            const int j = c >> 1;
            #pragma unroll
            for (int mt = 0; mt < 2; mt++) {
                const int r0 = bm + wm * 32 + mt * 16 + g;
                float ga0 = acc[mt][nt][0], up0 = acc[mt][nt][1];
                float ga1 = acc[mt][nt][2], up1 = acc[mt][nt][3];
                float m0 = ga0 / (1.f + __expf(-ga0)) * up0;
                float m1 = ga1 / (1.f + __expf(-ga1)) * up1;
                __nv_bfloat16 h0, l0, h1, l1;
                split_bf16(m0, h0, l0);
                split_bf16(m1, h1, l1);
                mh[(size_t)r0 * NW + j] = h0;
                ml[(size_t)r0 * NW + j] = l0;
                mh[(size_t)(r0 + 8) * NW + j] = h1;
                ml[(size_t)(r0 + 8) * NW + j] = l1;
            }
        }
    }
}

// ---------------- split + transpose fp32 W[K,N] -> bf16 hi/lo [N,K] ----------------
__global__ __launch_bounds__(256) void wsplit_kernel(
    const float* __restrict__ W, __nv_bfloat16* __restrict__ hi, __nv_bfloat16* __restrict__ lo,
    int K, int N)
{
    __shared__ float t[32][33];
    const int n0 = blockIdx.x * 32, k0 = blockIdx.y * 32;
    const int tx = threadIdx.x & 31, ty = threadIdx.x >> 5;
    #pragma unroll
    for (int i = ty; i < 32; i += 8)
        t[i][tx] = W[(size_t)(k0 + i) * N + n0 + tx];
    __syncthreads();
    #pragma unroll
    for (int i = ty; i < 32; i += 8) {
        float v = t[tx][i];
        __nv_bfloat16 h, l;
        split_bf16(v, h, l);
        size_t o = (size_t)(n0 + i) * K + k0 + tx;
        hi[o] = h; lo[o] = l;
    }
}

// ---------------- interleaved split+transpose of w_gate_up ----------------
__global__ __launch_bounds__(256) void wsplit_gu_kernel(
    const float* __restrict__ W, __nv_bfloat16* __restrict__ hi, __nv_bfloat16* __restrict__ lo,
    int K)
{
    __shared__ float t[32][33];
    const int n0 = blockIdx.x * 32, k0 = blockIdx.y * 32;
    const int tx = threadIdx.x & 31, ty = threadIdx.x >> 5;
    const int jbase = n0 >> 1;
    #pragma unroll
    for (int i = ty; i < 32; i += 8) {
        const int s = tx >> 4, jl = tx & 15;
        t[i][tx] = W[(size_t)(k0 + i) * (2 * DFF) + (size_t)s * DFF + jbase + jl];
    }
    __syncthreads();
    #pragma unroll
    for (int i = ty; i < 32; i += 8) {
        float v = t[tx][(i & 1) * 16 + (i >> 1)];
        __nv_bfloat16 h, l;
        split_bf16(v, h, l);
        size_t o = (size_t)(n0 + i) * K + k0 + tx;
        hi[o] = h; lo[o] = l;
    }
}

// ---------------- RMSNorm -> bf16 hi/lo (fused split) ----------------
__global__ __launch_bounds__(256) void rmsnorm_kernel(
    const float* __restrict__ x, const float* __restrict__ w,
    __nv_bfloat16* __restrict__ hi, __nv_bfloat16* __restrict__ lo)
{
    const int row = blockIdx.x;
    const int t = threadIdx.x;
    const float4* xr = (const float4*)(x + (size_t)row * DMODEL);
    float4 buf[4];
    float ss = 0.f;
    #pragma unroll
    for (int i = 0; i < 4; i++) {
        float4 v = xr[t + i * 256];
        buf[i] = v;
        ss += v.x*v.x + v.y*v.y + v.z*v.z + v.w*v.w;
    }
    __shared__ float red[8];
    #pragma unroll
    for (int o = 16; o > 0; o >>= 1) ss += __shfl_xor_sync(0xffffffffu, ss, o);
    if ((t & 31) == 0) red[t >> 5] = ss;
    __syncthreads();
    if (t < 32) {
        float v = (t < 8) ? red[t] : 0.f;
        #pragma unroll
        for (int o = 4; o > 0; o >>= 1) v += __shfl_xor_sync(0xffffffffu, v, o);
        if (t == 0) red[0] = v;
    }
    __syncthreads();
    const float inv = rsqrtf(red[0] * (1.f / DMODEL) + 1e-6f);
    const float4* wr = (const float4*)w;
    #pragma unroll
    for (int i = 0; i < 4; i++) {
        float4 v = buf[i];
        float4 ww = wr[t + i * 256];
        float f0 = v.x * inv * ww.x, f1 = v.y * inv * ww.y;
        float f2 = v.z * inv * ww.z, f3 = v.w * inv * ww.w;
        __nv_bfloat16 h0, l0, h1, l1, h2, l2, h3, l3;
        split_bf16(f0, h0, l0); split_bf16(f1, h1, l1);
        split_bf16(f2, h2, l2); split_bf16(f3, h3, l3);
        const size_t idx = (size_t)row * DMODEL + (t + i * 256) * 4;
        *(__nv_bfloat162*)(hi + idx)     = __nv_bfloat162(h0, h1);
        *(__nv_bfloat162*)(hi + idx + 2) = __nv_bfloat162(h2, h3);
        *(__nv_bfloat162*)(lo + idx)     = __nv_bfloat162(l0, l1);
        *(__nv_bfloat162*)(lo + idx + 2) = __nv_bfloat162(l2, l3);
    }
}

// ---------------- RoPE (in place, fp32) ----------------
__global__ __launch_bounds__(256) void rope_kernel(
    float* __restrict__ qkv, const int* __restrict__ pos)
{
    const int idx = blockIdx.x * 256 + threadIdx.x;
    const int i   = idx & 63;
    const int h   = (idx >> 6) & 31;
    const int tkn = idx >> 11;
    const float p = (float)pos[tkn];
    const float inv_freq = 1.f / powf(10000.f, (float)i * (1.f / 64.f));
    float sv, cv;
    sincosf(p * inv_freq, &sv, &cv);
    const size_t base = (size_t)tkn * QKVDIM + (size_t)h * DHEAD + i;
    float q1 = qkv[base], q2 = qkv[base + 64];
    qkv[base]      = q1 * cv - q2 * sv;
    qkv[base + 64] = q2 * cv + q1 * sv;
    float k1 = qkv[base + DMODEL], k2 = qkv[base + DMODEL + 64];
    qkv[base + DMODEL]      = k1 * cv - k2 * sv;
    qkv[base + DMODEL + 64] = k2 * cv + k1 * sv;
}

// ================= Flash attention (HMMA bf16-split, causal, ldmatrix) — R10 version =================
#define AQS 136
#define AVS 72
#define ATTN_ELEMS (2*(128*AQS) + 2*(64*AQS) + 2*(128*AVS))
#define ATTN_SMEM  (ATTN_ELEMS * 2)

__global__ __launch_bounds__(256) void attn_kernel(
    const float* __restrict__ qkv,
    __nv_bfloat16* __restrict__ ohi, __nv_bfloat16* __restrict__ olo)
{
    extern __shared__ __nv_bfloat16 smb[];
    __nv_bfloat16* Qh = smb;
    __nv_bfloat16* Ql = Qh + 128 * AQS;
    __nv_bfloat16* Kh = Ql + 128 * AQS;
    __nv_bfloat16* Kl = Kh + 64 * AQS;
    __nv_bfloat16* Vh = Kl + 64 * AQS;
    __nv_bfloat16* Vl = Vh + 128 * AVS;
    const uint32_t sQh = smem_u32(Qh), sQl = smem_u32(Ql);
    const uint32_t sKh = smem_u32(Kh), sKl = smem_u32(Kl);
    const uint32_t sVh = smem_u32(Vh), sVl = smem_u32(Vl);

    const int q0 = (gridDim.x - 1 - blockIdx.x) * 128;
    const int h  = blockIdx.y;
    const int b  = blockIdx.z;
    const int tid = threadIdx.x;
    const int wid = tid >> 5, lane = tid & 31;
    const int g = lane >> 2, tig = lane & 3;
    const int rsel = lane & 15, kh = lane >> 4;
    const int brow = lane & 7, bkh = (lane >> 3) & 1;
    const float scale = 0.08838834764831845f;

    const size_t base = (size_t)(b * SEQ) * QKVDIM + (size_t)h * DHEAD;
    const int lr0 = tid >> 5, lc4 = (tid & 31) << 2;

    for (int idx = tid; idx < 128 * 32; idx += 256) {
        const int r = idx >> 5, c4 = (idx & 31) << 2;
        float4 v = *(const float4*)(qkv + base + (size_t)(q0 + r) * QKVDIM + c4);
        __nv_bfloat16 h0, l0, h1, l1, h2, l2, h3, l3;
        split_bf16(v.x, h0, l0); split_bf16(v.y, h1, l1);
        split_bf16(v.z, h2, l2); split_bf16(v.w, h3, l3);
        __nv_bfloat162* ph = (__nv_bfloat162*)(Qh + r * AQS + c4);
        __nv_bfloat162* pl = (__nv_bfloat162*)(Ql + r * AQS + c4);
        ph[0] = __nv_bfloat162(h0, h1); ph[1] = __nv_bfloat162(h2, h3);
        pl[0] = __nv_bfloat162(l0, l1); pl[1] = __nv_bfloat162(l2, l3);
    }

    float o[16][4];
    #pragma unroll
    for (int on = 0; on < 16; on++)
        #pragma unroll
        for (int e = 0; e < 4; e++) o[on][e] = 0.f;
    float m_i[2] = {-1e30f, -1e30f}, l_i[2] = {0.f, 0.f};

    const int ntk = q0 / 64 + 2;
    float4 kreg[8], vreg[8];

    #pragma unroll
    for (int i = 0; i < 8; i++)
        kreg[i] = *(const float4*)(qkv + base + (size_t)(lr0 + i * 8) * QKVDIM + DMODEL + lc4);

    for (int kt = 0; kt < ntk; kt++) {
        const int k0 = kt * 64;
        __syncthreads();

        #pragma unroll
        for (int i = 0; i < 8; i++) {
            const int r = lr0 + i * 8;
            float4 kv = kreg[i];
            __nv_bfloat16 h0, l0, h1, l1, h2, l2, h3, l3;
            split_bf16(kv.x, h0, l0); split_bf16(kv.y, h1, l1);
            split_bf16(kv.z, h2, l2); split_bf16(kv.w, h3, l3);
            __nv_bfloat162* ph = (__nv_bfloat162*)(Kh + r * AQS + lc4);
            __nv_bfloat162* pl = (__nv_bfloat162*)(Kl + r * AQS + lc4);
            ph[0] = __nv_bfloat162(h0, h1); ph[1] = __nv_bfloat162(h2, h3);
            pl[0] = __nv_bfloat162(l0, l1); pl[1] = __nv_bfloat162(l2, l3);
        }
        #pragma unroll
        for (int i = 0; i < 8; i++)
            vreg[i] = *(const float4*)(qkv + base + (size_t)(k0 + lr0 + i * 8) * QKVDIM
                                       + 2 * DMODEL + lc4);
        __syncthreads();

        if (kt + 1 < ntk) {
            const int k1 = (kt + 1) * 64;
            #pragma unroll
            for (int i = 0; i < 8; i++)
                kreg[i] = *(const float4*)(qkv + base + (size_t)(k1 + lr0 + i * 8) * QKVDIM
                                           + DMODEL + lc4);
        }

        float s[8][4];
        #pragma unroll
        for (int nt = 0; nt < 8; nt++)
            #pragma unroll
            for (int e = 0; e < 4; e++) s[nt][e] = 0.f;
        #pragma unroll
        for (int ks = 0; ks < 8; ks++) {
            uint32_t ah[4], al[4];
            const uint32_t qo = (uint32_t)(((wid * 16 + rsel) * AQS + (ks << 4) + kh * 8) * 2);
            ldsm_x4(ah, sQh + qo);
            ldsm_x4(al, sQl + qo);
            #pragma unroll
            for (int nt = 0; nt < 8; nt++) {
                const uint32_t ko = (uint32_t)(((nt * 8 + brow) * AQS + (ks << 4) + bkh * 8) * 2);
                uint32_t bh[2], bl[2];
                ldsm_x2(bh, sKh + ko);
                ldsm_x2(bl, sKl + ko);
                mma16816(s[nt], ah, bh);
                mma16816(s[nt], al, bh);
                mma16816(s[nt], ah, bl);
            }
        }

        const bool need_mask = (kt >= ntk - 2);
        #pragma unroll
        for (int rr = 0; rr < 2; rr++) {
            const int qrow = q0 + wid * 16 + g + rr * 8;
            float rmax = -1e30f;
            #pragma unroll
            for (int nt = 0; nt < 8; nt++) {
                #pragma unroll
                for (int j = 0; j < 2; j++) {
                    float v = s[nt][rr * 2 + j] * scale;
                    if (need_mask && (k0 + nt * 8 + tig * 2 + j > qrow)) v = -1e30f;
                    s[nt][rr * 2 + j] = v;
                    rmax = fmaxf(rmax, v);
                }
            }
            rmax = fmaxf(rmax, __shfl_xor_sync(0xffffffffu, rmax, 1));
            rmax = fmaxf(rmax, __shfl_xor_sync(0xffffffffu, rmax, 2));
            const float mnew = fmaxf(m_i[rr], rmax);
            const float alpha = __expf(m_i[rr] - mnew);
            m_i[rr] = mnew;
            float rsum = 0.f;
            #pragma unroll
            for (int nt = 0; nt < 8; nt++) {
                #pragma unroll
                for (int j = 0; j < 2; j++) {
                    float p = __expf(s[nt][rr * 2 + j] - mnew);
                    s[nt][rr * 2 + j] = p;
                    rsum += p;
                }
            }
            rsum += __shfl_xor_sync(0xffffffffu, rsum, 1);
            rsum += __shfl_xor_sync(0xffffffffu, rsum, 2);
            l_i[rr] = l_i[rr] * alpha + rsum;
            #pragma unroll
            for (int on = 0; on < 16; on++) {
                o[on][rr * 2]     *= alpha;
                o[on][rr * 2 + 1] *= alpha;
            }
        }

        #pragma unroll
        for (int i = 0; i < 8; i++) {
            const int r = lr0 + i * 8;
            float4 vv = vreg[i];
            float vf[4] = {vv.x, vv.y, vv.z, vv.w};
            #pragma unroll
            for (int j = 0; j < 4; j++) {
                __nv_bfloat16 vh, vlo;
                split_bf16(vf[j], vh, vlo);
                Vh[(lc4 + j) * AVS + r] = vh;
                Vl[(lc4 + j) * AVS + r] = vlo;
            }
        }
        __syncthreads();

        #pragma unroll
        for (int ks2 = 0; ks2 < 4; ks2++) {
            uint32_t pah[4], pal[4];
            #pragma unroll
            for (int half = 0; half < 2; half++) {
                const int nt = 2 * ks2 + half;
                #pragma unroll
                for (int rr = 0; rr < 2; rr++) {
                    float p0 = s[nt][rr * 2], p1 = s[nt][rr * 2 + 1];
                    __nv_bfloat16 h0 = __float2bfloat16(p0);
                    __nv_bfloat16 h1 = __float2bfloat16(p1);
                    __nv_bfloat162 hh = __nv_bfloat162(h0, h1);
                    pah[half * 2 + rr] = *(uint32_t*)&hh;
                    __nv_bfloat162 ll = __nv_bfloat162(
                        __float2bfloat16(p0 - __bfloat162float(h0)),
                        __float2bfloat16(p1 - __bfloat162float(h1)));
                    pal[half * 2 + rr] = *(uint32_t*)&ll;
                }
            }
            #pragma unroll
            for (int on = 0; on < 16; on++) {
                const uint32_t vo = (uint32_t)(((on * 8 + brow) * AVS + (ks2 << 4) + bkh * 8) * 2);
                uint32_t bh[2], bl[2];
                ldsm_x2(bh, sVh + vo);
                ldsm_x2(bl, sVl + vo);
                mma16816(o[on], pah, bh);
                mma16816(o[on], pah, bl);
                mma16816(o[on], pal, bh);
            }
        }
    }

    #pragma unroll
    for (int rr = 0; rr < 2; rr++) {
        const float inv = 1.f / l_i[rr];
        const size_t tok = (size_t)(b * SEQ + q0 + wid * 16 + g + rr * 8);
        #pragma unroll
        for (int on = 0; on < 16; on++) {
            const float v0 = o[on][rr * 2] * inv;
            const float v1 = o[on][rr * 2 + 1] * inv;
            __nv_bfloat16 h0, l0, h1, l1;
            split_bf16(v0, h0, l0);
            split_bf16(v1, h1, l1);
            const size_t idx = tok * DMODEL + (size_t)h * DHEAD + on * 8 + tig * 2;
            *(__nv_bfloat162*)(ohi + idx) = __nv_bfloat162(h0, h1);
            *(__nv_bfloat162*)(olo + idx) = __nv_bfloat162(l0, l1);
        }
    }
}

// ---------------- launch ----------------
extern "C" void kernel_launch(void* const* d_in, const int* in_sizes, int n_in,
                              void* d_out, int out_size)
{
    const float* hs    = (const float*)d_in[0];
    const int*   pos   = (const int*)  d_in[1];
    const float* ln1w  = (const float*)d_in[2];
    const float* wqkv  = (const float*)d_in[3];
    const float* bqkv  = (const float*)d_in[4];
    const float* wo    = (const float*)d_in[5];
    const float* ln2w  = (const float*)d_in[6];
    const float* wgu   = (const float*)d_in[7];
    const float* wdown = (const float*)d_in[8];
    float* out = (float*)d_out;

    float *qkv, *hidden;
    __nv_bfloat16 *ahi, *alo, *bhi, *blo;
    cudaGetSymbolAddress((void**)&qkv,    g_qkv);
    cudaGetSymbolAddress((void**)&hidden, g_hidden);
    cudaGetSymbolAddress((void**)&ahi,    g_ahi);
    cudaGetSymbolAddress((void**)&alo,    g_alo);
    cudaGetSymbolAddress((void**)&bhi,    g_bhi);
    cudaGetSymbolAddress((void**)&blo,    g_blo);

    cudaFuncSetAttribute(attn_kernel, cudaFuncAttributeMaxDynamicSharedMemorySize, ATTN_SMEM);
    cudaFuncSetAttribute(mma_gemm_kernel<0>, cudaFuncAttributeMaxDynamicSharedMemorySize, GSMEM);
    cudaFuncSetAttribute(mma_gemm_kernel<1>, cudaFuncAttributeMaxDynamicSharedMemorySize, GSMEM);

    // 1. x = rmsnorm(hs) -> ahi/alo
    rmsnorm_kernel<<<TOKENS, 256>>>(hs, ln1w, ahi, alo);
    // 2. qkv = x @ w_qkv + b
    wsplit_kernel<<<dim3(QKVDIM / 32, DMODEL / 32), 256>>>(wqkv, bhi, blo, DMODEL, QKVDIM);
    mma_gemm_kernel<0><<<(TOKENS / 128) * (QKVDIM / 256), 512, GSMEM>>>(
        TOKENS, QKVDIM, DMODEL, ahi, alo, bhi, blo, qkv, bqkv, nullptr, nullptr, nullptr);
    // 3. rope (in place)
    rope_kernel<<<(TOKENS * NHEADS * 64) / 256, 256>>>(qkv, pos);
    // 4. attention -> ahi/alo
    attn_kernel<<<dim3(SEQ / 128, NHEADS, NBATCH), 256, ATTN_SMEM>>>(qkv, ahi, alo);
    // 5. hidden = hs + attnout @ w_o
    wsplit_kernel<<<dim3(DMODEL / 32, DMODEL / 32), 256>>>(wo, bhi, blo, DMODEL, DMODEL);
    mma_gemm_kernel<0><<<(TOKENS / 128) * (DMODEL / 256), 512, GSMEM>>>(
        TOKENS, DMODEL, DMODEL, ahi, alo, bhi, blo, hidden, nullptr, hs, nullptr, nullptr);
    // 6. x = rmsnorm(hidden) -> ahi/alo
    rmsnorm_kernel<<<TOKENS, 256>>>(hidden, ln2w, ahi, alo);
    // 7. gate_up GEMM (interleaved weights) + fused silu -> mid (bf16 halves of g_qkv; attention data dead)
    {
        __nv_bfloat16* mhi = (__nv_bfloat16*)qkv;
        __nv_bfloat16* mlo = (__nv_bfloat16*)qkv + (size_t)TOKENS * DFF;
        wsplit_gu_kernel<<<dim3((2 * DFF) / 32, DMODEL / 32), 256>>>(wgu, bhi, blo, DMODEL);
        mma_gemm_kernel<1><<<(TOKENS / 128) * ((2 * DFF) / 256), 512, GSMEM>>>(
            TOKENS, 2 * DFF, DMODEL, ahi, alo, bhi, blo, nullptr, nullptr, nullptr, mhi, mlo);
        // 8. out = hidden + mid @ w_down
        wsplit_kernel<<<dim3(DMODEL / 32, DFF / 32), 256>>>(wdown, bhi, blo, DFF, DMODEL);
        mma_gemm_kernel<0><<<(TOKENS / 128) * (DMODEL / 256), 512, GSMEM>>>(
            TOKENS, DMODEL, DFF, mhi, mlo, bhi, blo, out, nullptr, hidden, nullptr, nullptr);
    }
}

// round 16
// speedup vs baseline: 1.1733x; 1.1733x over previous
#include <cuda_runtime.h>
#include <cuda_bf16.h>
#include <cstdint>
#include <math.h>

#define TOKENS 4096
#define DMODEL 4096
#define SEQ    2048
#define NBATCH 2
#define NHEADS 32
#define DHEAD  128
#define DFF    11008
#define QKVDIM (3*DMODEL)

// ---------------- scratch (device globals: allocation-free) ----------------
__device__ float g_qkv    [(size_t)TOKENS * QKVDIM];
__device__ float g_hidden [(size_t)TOKENS * DMODEL];
__device__ float g_gu     [(size_t)TOKENS * 2 * DFF];
__device__ __nv_bfloat16 g_ahi[(size_t)TOKENS * DFF];
__device__ __nv_bfloat16 g_alo[(size_t)TOKENS * DFF];
__device__ __nv_bfloat16 g_bhi[(size_t)(2*DFF) * DMODEL];
__device__ __nv_bfloat16 g_blo[(size_t)(2*DFF) * DMODEL];

// ================= helpers =================
__device__ __forceinline__ uint32_t smem_u32(const void* p) {
    uint32_t a;
    asm("{ .reg .u64 t; cvta.to.shared.u64 t, %1; cvt.u32.u64 %0, t; }" : "=r"(a) : "l"(p));
    return a;
}
#define CP_ASYNC16(s, g) asm volatile("cp.async.cg.shared.global [%0], [%1], 16;" :: "r"(s), "l"(g))
#define CP_COMMIT() asm volatile("cp.async.commit_group;" ::: "memory")
#define CP_WAIT0()  asm volatile("cp.async.wait_group 0;" ::: "memory")
#define CP_WAIT1()  asm volatile("cp.async.wait_group 1;" ::: "memory")

__device__ __forceinline__ void ldsm_x4(uint32_t* r, uint32_t addr) {
    asm volatile("ldmatrix.sync.aligned.m8n8.x4.shared.b16 {%0,%1,%2,%3}, [%4];"
        : "=r"(r[0]), "=r"(r[1]), "=r"(r[2]), "=r"(r[3]) : "r"(addr));
}
__device__ __forceinline__ void ldsm_x2(uint32_t* r, uint32_t addr) {
    asm volatile("ldmatrix.sync.aligned.m8n8.x2.shared.b16 {%0,%1}, [%2];"
        : "=r"(r[0]), "=r"(r[1]) : "r"(addr));
}
__device__ __forceinline__ void mma16816(float* c, const uint32_t* a, const uint32_t* b) {
    asm volatile(
        "mma.sync.aligned.m16n8k16.row.col.f32.bf16.bf16.f32 "
        "{%0,%1,%2,%3}, {%4,%5,%6,%7}, {%8,%9}, {%0,%1,%2,%3};"
        : "+f"(c[0]), "+f"(c[1]), "+f"(c[2]), "+f"(c[3])
        : "r"(a[0]), "r"(a[1]), "r"(a[2]), "r"(a[3]), "r"(b[0]), "r"(b[1]));
}
__device__ __forceinline__ void split_bf16(float v, __nv_bfloat16& h, __nv_bfloat16& l) {
    h = __float2bfloat16(v);
    l = __float2bfloat16(v - __bfloat162float(h));
}

// ================= HMMA GEMM (bf16 split, fp32 acc) — R8 mainloop (do not touch) =================
#define LDAB   40
#define TILEB  (128 * LDAB * 2)
#define OFF_AH 0
#define OFF_AL TILEB
#define OFF_BH (2*TILEB)
#define OFF_BL (3*TILEB)
#define BUFB   (4*TILEB)
#define GSMEM  (2*BUFB)
#define RASTG  8

__device__ __forceinline__ void g2s_tile(uint32_t dst, const __nv_bfloat16* src,
                                         int row0, int K, int k0, int tid)
{
    #pragma unroll
    for (int it = 0; it < 2; it++) {
        int idx = tid + it * 256;
        int r = idx >> 2, c8 = (idx & 3) << 3;
        CP_ASYNC16(dst + r * 80 + (c8 << 1),
                   (const char*)(src + (size_t)(row0 + r) * K + k0 + c8));
    }
}

__global__ __launch_bounds__(256, 2) void mma_gemm_kernel(
    int M, int N, int K,
    const __nv_bfloat16* __restrict__ Ah, const __nv_bfloat16* __restrict__ Al,
    const __nv_bfloat16* __restrict__ Bh, const __nv_bfloat16* __restrict__ Bl,
    float* __restrict__ C, const float* __restrict__ bias, const float* __restrict__ res)
{
    extern __shared__ char smem[];
    const uint32_t sb = smem_u32(smem);
    const int tid = threadIdx.x;
    const int wid = tid >> 5, lane = tid & 31;
    const int g = lane >> 2, tig = lane & 3;
    const int wm = wid & 3, wn = wid >> 2;

    const int NB = N >> 7, MB = M >> 7;
    const int bid = blockIdx.x;
    const int per_group = RASTG * NB;
    const int group = bid / per_group;
    const int first_m = group * RASTG;
    const int gsz = min(RASTG, MB - first_m);
    const int rem = bid - group * per_group;
    const int bm = (first_m + rem % gsz) << 7;
    const int bn = (rem / gsz) << 7;

    const int rsel = lane & 15;
    const int kh   = lane >> 4;
    const int brow = lane & 7;
    const int bkh  = (lane >> 3) & 1;

    float acc[2][8][4];
    #pragma unroll
    for (int mt = 0; mt < 2; mt++)
        #pragma unroll
        for (int nt = 0; nt < 8; nt++)
            #pragma unroll
            for (int e = 0; e < 4; e++) acc[mt][nt][e] = 0.f;

    const int NC = K >> 5;
    g2s_tile(sb + OFF_AH, Ah, bm, K, 0, tid);
    g2s_tile(sb + OFF_AL, Al, bm, K, 0, tid);
    g2s_tile(sb + OFF_BH, Bh, bn, K, 0, tid);
    g2s_tile(sb + OFF_BL, Bl, bn, K, 0, tid);
    CP_COMMIT();

    for (int ck = 0; ck < NC; ck++) {
        if (ck + 1 < NC) {
            const uint32_t nb = sb + (uint32_t)((ck + 1) & 1) * BUFB;
            const int k1 = (ck + 1) << 5;
            g2s_tile(nb + OFF_AH, Ah, bm, K, k1, tid);
            g2s_tile(nb + OFF_AL, Al, bm, K, k1, tid);
            g2s_tile(nb + OFF_BH, Bh, bn, K, k1, tid);
            g2s_tile(nb + OFF_BL, Bl, bn, K, k1, tid);
            CP_COMMIT();
            CP_WAIT1();
        } else {
            CP_WAIT0();
        }
        __syncthreads();

        const uint32_t bb = sb + (uint32_t)(ck & 1) * BUFB;
        #pragma unroll
        for (int ks = 0; ks < 2; ks++) {
            uint32_t ahf[2][4], alf[2][4];
            #pragma unroll
            for (int mt = 0; mt < 2; mt++) {
                const uint32_t ao = (uint32_t)((wm * 32 + mt * 16 + rsel) * 80
                                               + ((ks << 4) + kh * 8) * 2);
                ldsm_x4(ahf[mt], bb + OFF_AH + ao);
                ldsm_x4(alf[mt], bb + OFF_AL + ao);
            }
            #pragma unroll
            for (int nt = 0; nt < 8; nt++) {
                const uint32_t bo = (uint32_t)((wn * 64 + nt * 8 + brow) * 80
                                               + ((ks << 4) + bkh * 8) * 2);
                uint32_t bh[2], bl[2];
                ldsm_x2(bh, bb + OFF_BH + bo);
                ldsm_x2(bl, bb + OFF_BL + bo);
                #pragma unroll
                for (int mt = 0; mt < 2; mt++) {
                    mma16816(acc[mt][nt], ahf[mt], bh);
                    mma16816(acc[mt][nt], alf[mt], bh);
                    mma16816(acc[mt][nt], ahf[mt], bl);
                }
            }
        }
        __syncthreads();
    }

    #pragma unroll
    for (int nt = 0; nt < 8; nt++) {
        const int c = bn + wn * 64 + nt * 8 + (tig << 1);
        float bx = 0.f, by = 0.f;
        if (bias) { bx = bias[c]; by = bias[c + 1]; }
        #pragma unroll
        for (int mt = 0; mt < 2; mt++) {
            const int r0 = bm + wm * 32 + mt * 16 + g;
            float2 v0 = make_float2(acc[mt][nt][0] + bx, acc[mt][nt][1] + by);
            float2 v1 = make_float2(acc[mt][nt][2] + bx, acc[mt][nt][3] + by);
            size_t g0 = (size_t)r0 * N + c;
            size_t g1 = (size_t)(r0 + 8) * N + c;
            if (res) {
                float2 r0v = *(const float2*)(res + g0);
                float2 r1v = *(const float2*)(res + g1);
                v0.x += r0v.x; v0.y += r0v.y; v1.x += r1v.x; v1.y += r1v.y;
            }
            *(float2*)(C + g0) = v0;
            *(float2*)(C + g1) = v1;
        }
    }
}

// ---------------- split + transpose fp32 W[K,N] -> bf16 hi/lo [N,K] ----------------
__global__ __launch_bounds__(256) void wsplit_kernel(
    const float* __restrict__ W, __nv_bfloat16* __restrict__ hi, __nv_bfloat16* __restrict__ lo,
    int K, int N)
{
    __shared__ float t[32][33];
    const int n0 = blockIdx.x * 32, k0 = blockIdx.y * 32;
    const int tx = threadIdx.x & 31, ty = threadIdx.x >> 5;
    #pragma unroll
    for (int i = ty; i < 32; i += 8)
        t[i][tx] = W[(size_t)(k0 + i) * N + n0 + tx];
    __syncthreads();
    #pragma unroll
    for (int i = ty; i < 32; i += 8) {
        float v = t[tx][i];
        __nv_bfloat16 h, l;
        split_bf16(v, h, l);
        size_t o = (size_t)(n0 + i) * K + k0 + tx;
        hi[o] = h; lo[o] = l;
    }
}

// ---------------- RMSNorm -> bf16 hi/lo (fused split) ----------------
__global__ __launch_bounds__(256) void rmsnorm_kernel(
    const float* __restrict__ x, const float* __restrict__ w,
    __nv_bfloat16* __restrict__ hi, __nv_bfloat16* __restrict__ lo)
{
    const int row = blockIdx.x;
    const int t = threadIdx.x;
    const float4* xr = (const float4*)(x + (size_t)row * DMODEL);
    float4 buf[4];
    float ss = 0.f;
    #pragma unroll
    for (int i = 0; i < 4; i++) {
        float4 v = xr[t + i * 256];
        buf[i] = v;
        ss += v.x*v.x + v.y*v.y + v.z*v.z + v.w*v.w;
    }
    __shared__ float red[8];
    #pragma unroll
    for (int o = 16; o > 0; o >>= 1) ss += __shfl_xor_sync(0xffffffffu, ss, o);
    if ((t & 31) == 0) red[t >> 5] = ss;
    __syncthreads();
    if (t < 32) {
        float v = (t < 8) ? red[t] : 0.f;
        #pragma unroll
        for (int o = 4; o > 0; o >>= 1) v += __shfl_xor_sync(0xffffffffu, v, o);
        if (t == 0) red[0] = v;
    }
    __syncthreads();
    const float inv = rsqrtf(red[0] * (1.f / DMODEL) + 1e-6f);
    const float4* wr = (const float4*)w;
    #pragma unroll
    for (int i = 0; i < 4; i++) {
        float4 v = buf[i];
        float4 ww = wr[t + i * 256];
        float f0 = v.x * inv * ww.x, f1 = v.y * inv * ww.y;
        float f2 = v.z * inv * ww.z, f3 = v.w * inv * ww.w;
        __nv_bfloat16 h0, l0, h1, l1, h2, l2, h3, l3;
        split_bf16(f0, h0, l0); split_bf16(f1, h1, l1);
        split_bf16(f2, h2, l2); split_bf16(f3, h3, l3);
        const size_t idx = (size_t)row * DMODEL + (t + i * 256) * 4;
        *(__nv_bfloat162*)(hi + idx)     = __nv_bfloat162(h0, h1);
        *(__nv_bfloat162*)(hi + idx + 2) = __nv_bfloat162(h2, h3);
        *(__nv_bfloat162*)(lo + idx)     = __nv_bfloat162(l0, l1);
        *(__nv_bfloat162*)(lo + idx + 2) = __nv_bfloat162(l2, l3);
    }
}

// ---------------- RoPE (in place, fp32) ----------------
__global__ __launch_bounds__(256) void rope_kernel(
    float* __restrict__ qkv, const int* __restrict__ pos)
{
    const int idx = blockIdx.x * 256 + threadIdx.x;
    const int i   = idx & 63;
    const int h   = (idx >> 6) & 31;
    const int tkn = idx >> 11;
    const float p = (float)pos[tkn];
    const float inv_freq = 1.f / powf(10000.f, (float)i * (1.f / 64.f));
    float sv, cv;
    sincosf(p * inv_freq, &sv, &cv);
    const size_t base = (size_t)tkn * QKVDIM + (size_t)h * DHEAD + i;
    float q1 = qkv[base], q2 = qkv[base + 64];
    qkv[base]      = q1 * cv - q2 * sv;
    qkv[base + 64] = q2 * cv + q1 * sv;
    float k1 = qkv[base + DMODEL], k2 = qkv[base + DMODEL + 64];
    qkv[base + DMODEL]      = k1 * cv - k2 * sv;
    qkv[base + DMODEL + 64] = k2 * cv + k1 * sv;
}

// ================= Flash attention (HMMA, causal, ldmatrix) =================
// S = QhKh + QlKh + QhKl (3-term).  PV = PhVh + PlVh (2-term: V-residual dropped;
// P >= 0 and sums to 1 so the dropped term is bounded by 2^-9 * weighted |V|).
// No Vl tile: less smem, fewer splits, 1/6 fewer total MMAs.
#define AQS 136
#define AVS 72
#define ATTN_ELEMS (2*(128*AQS) + 2*(64*AQS) + (128*AVS))
#define ATTN_SMEM  (ATTN_ELEMS * 2)

__global__ __launch_bounds__(256) void attn_kernel(
    const float* __restrict__ qkv,
    __nv_bfloat16* __restrict__ ohi, __nv_bfloat16* __restrict__ olo)
{
    extern __shared__ __nv_bfloat16 smb[];
    __nv_bfloat16* Qh = smb;
    __nv_bfloat16* Ql = Qh + 128 * AQS;
    __nv_bfloat16* Kh = Ql + 128 * AQS;
    __nv_bfloat16* Kl = Kh + 64 * AQS;
    __nv_bfloat16* Vh = Kl + 64 * AQS;
    const uint32_t sQh = smem_u32(Qh), sQl = smem_u32(Ql);
    const uint32_t sKh = smem_u32(Kh), sKl = smem_u32(Kl);
    const uint32_t sVh = smem_u32(Vh);

    const int q0 = (gridDim.x - 1 - blockIdx.x) * 128;
    const int h  = blockIdx.y;
    const int b  = blockIdx.z;
    const int tid = threadIdx.x;
    const int wid = tid >> 5, lane = tid & 31;
    const int g = lane >> 2, tig = lane & 3;
    const int rsel = lane & 15, kh = lane >> 4;
    const int brow = lane & 7, bkh = (lane >> 3) & 1;
    const float scale = 0.08838834764831845f;

    const size_t base = (size_t)(b * SEQ) * QKVDIM + (size_t)h * DHEAD;
    const int lr0 = tid >> 5, lc4 = (tid & 31) << 2;

    for (int idx = tid; idx < 128 * 32; idx += 256) {
        const int r = idx >> 5, c4 = (idx & 31) << 2;
        float4 v = *(const float4*)(qkv + base + (size_t)(q0 + r) * QKVDIM + c4);
        __nv_bfloat16 h0, l0, h1, l1, h2, l2, h3, l3;
        split_bf16(v.x, h0, l0); split_bf16(v.y, h1, l1);
        split_bf16(v.z, h2, l2); split_bf16(v.w, h3, l3);
        __nv_bfloat162* ph = (__nv_bfloat162*)(Qh + r * AQS + c4);
        __nv_bfloat162* pl = (__nv_bfloat162*)(Ql + r * AQS + c4);
        ph[0] = __nv_bfloat162(h0, h1); ph[1] = __nv_bfloat162(h2, h3);
        pl[0] = __nv_bfloat162(l0, l1); pl[1] = __nv_bfloat162(l2, l3);
    }

    float o[16][4];
    #pragma unroll
    for (int on = 0; on < 16; on++)
        #pragma unroll
        for (int e = 0; e < 4; e++) o[on][e] = 0.f;
    float m_i[2] = {-1e30f, -1e30f}, l_i[2] = {0.f, 0.f};

    const int ntk = q0 / 64 + 2;
    float4 kreg[8], vreg[8];

    #pragma unroll
    for (int i = 0; i < 8; i++)
        kreg[i] = *(const float4*)(qkv + base + (size_t)(lr0 + i * 8) * QKVDIM + DMODEL + lc4);

    for (int kt = 0; kt < ntk; kt++) {
        const int k0 = kt * 64;
        __syncthreads();

        #pragma unroll
        for (int i = 0; i < 8; i++) {
            const int r = lr0 + i * 8;
            float4 kv = kreg[i];
            __nv_bfloat16 h0, l0, h1, l1, h2, l2, h3, l3;
            split_bf16(kv.x, h0, l0); split_bf16(kv.y, h1, l1);
            split_bf16(kv.z, h2, l2); split_bf16(kv.w, h3, l3);
            __nv_bfloat162* ph = (__nv_bfloat162*)(Kh + r * AQS + lc4);
            __nv_bfloat162* pl = (__nv_bfloat162*)(Kl + r * AQS + lc4);
            ph[0] = __nv_bfloat162(h0, h1); ph[1] = __nv_bfloat162(h2, h3);
            pl[0] = __nv_bfloat162(l0, l1); pl[1] = __nv_bfloat162(l2, l3);
        }
        #pragma unroll
        for (int i = 0; i < 8; i++)
            vreg[i] = *(const float4*)(qkv + base + (size_t)(k0 + lr0 + i * 8) * QKVDIM
                                       + 2 * DMODEL + lc4);
        __syncthreads();

        if (kt + 1 < ntk) {
            const int k1 = (kt + 1) * 64;
            #pragma unroll
            for (int i = 0; i < 8; i++)
                kreg[i] = *(const float4*)(qkv + base + (size_t)(k1 + lr0 + i * 8) * QKVDIM
                                           + DMODEL + lc4);
        }

        float s[8][4];
        #pragma unroll
        for (int nt = 0; nt < 8; nt++)
            #pragma unroll
            for (int e = 0; e < 4; e++) s[nt][e] = 0.f;
        #pragma unroll
        for (int ks = 0; ks < 8; ks++) {
            uint32_t ah[4], al[4];
            const uint32_t qo = (uint32_t)(((wid * 16 + rsel) * AQS + (ks << 4) + kh * 8) * 2);
            ldsm_x4(ah, sQh + qo);
            ldsm_x4(al, sQl + qo);
            #pragma unroll
            for (int nt = 0; nt < 8; nt++) {
                const uint32_t ko = (uint32_t)(((nt * 8 + brow) * AQS + (ks << 4) + bkh * 8) * 2);
                uint32_t bh[2], bl[2];
                ldsm_x2(bh, sKh + ko);
                ldsm_x2(bl, sKl + ko);
                mma16816(s[nt], ah, bh);
                mma16816(s[nt], al, bh);
                mma16816(s[nt], ah, bl);
            }
        }

        const bool need_mask = (kt >= ntk - 2);
        #pragma unroll
        for (int rr = 0; rr < 2; rr++) {
            const int qrow = q0 + wid * 16 + g + rr * 8;
            float rmax = -1e30f;
            #pragma unroll
            for (int nt = 0; nt < 8; nt++) {
                #pragma unroll
                for (int j = 0; j < 2; j++) {
                    float v = s[nt][rr * 2 + j] * scale;
                    if (need_mask && (k0 + nt * 8 + tig * 2 + j > qrow)) v = -1e30f;
                    s[nt][rr * 2 + j] = v;
                    rmax = fmaxf(rmax, v);
                }
            }
            rmax = fmaxf(rmax, __shfl_xor_sync(0xffffffffu, rmax, 1));
            rmax = fmaxf(rmax, __shfl_xor_sync(0xffffffffu, rmax, 2));
            const float mnew = fmaxf(m_i[rr], rmax);
            const float alpha = __expf(m_i[rr] - mnew);
            m_i[rr] = mnew;
            float rsum = 0.f;
            #pragma unroll
            for (int nt = 0; nt < 8; nt++) {
                #pragma unroll
                for (int j = 0; j < 2; j++) {
                    float p = __expf(s[nt][rr * 2 + j] - mnew);
                    s[nt][rr * 2 + j] = p;
                    rsum += p;
                }
            }
            rsum += __shfl_xor_sync(0xffffffffu, rsum, 1);
            rsum += __shfl_xor_sync(0xffffffffu, rsum, 2);
            l_i[rr] = l_i[rr] * alpha + rsum;
            #pragma unroll
            for (int on = 0; on < 16; on++) {
                o[on][rr * 2]     *= alpha;
                o[on][rr * 2 + 1] *= alpha;
            }
        }

        // store V (hi only) transposed
        #pragma unroll
        for (int i = 0; i < 8; i++) {
            const int r = lr0 + i * 8;
            float4 vv = vreg[i];
            float vf[4] = {vv.x, vv.y, vv.z, vv.w};
            #pragma unroll
            for (int j = 0; j < 4; j++)
                Vh[(lc4 + j) * AVS + r] = __float2bfloat16(vf[j]);
        }
        __syncthreads();

        #pragma unroll
        for (int ks2 = 0; ks2 < 4; ks2++) {
            uint32_t pah[4], pal[4];
            #pragma unroll
            for (int half = 0; half < 2; half++) {
                const int nt = 2 * ks2 + half;
                #pragma unroll
                for (int rr = 0; rr < 2; rr++) {
                    float p0 = s[nt][rr * 2], p1 = s[nt][rr * 2 + 1];
                    __nv_bfloat16 h0 = __float2bfloat16(p0);
                    __nv_bfloat16 h1 = __float2bfloat16(p1);
                    __nv_bfloat162 hh = __nv_bfloat162(h0, h1);
                    pah[half * 2 + rr] = *(uint32_t*)&hh;
                    __nv_bfloat162 ll = __nv_bfloat162(
                        __float2bfloat16(p0 - __bfloat162float(h0)),
                        __float2bfloat16(p1 - __bfloat162float(h1)));
                    pal[half * 2 + rr] = *(uint32_t*)&ll;
                }
            }
            #pragma unroll
            for (int on = 0; on < 16; on++) {
                const uint32_t vo = (uint32_t)(((on * 8 + brow) * AVS + (ks2 << 4) + bkh * 8) * 2);
                uint32_t bh[2];
                ldsm_x2(bh, sVh + vo);
                mma16816(o[on], pah, bh);
                mma16816(o[on], pal, bh);
            }
        }
    }

    #pragma unroll
    for (int rr = 0; rr < 2; rr++) {
        const float inv = 1.f / l_i[rr];
        const size_t tok = (size_t)(b * SEQ + q0 + wid * 16 + g + rr * 8);
        #pragma unroll
        for (int on = 0; on < 16; on++) {
            const float v0 = o[on][rr * 2] * inv;
            const float v1 = o[on][rr * 2 + 1] * inv;
            __nv_bfloat16 h0, l0, h1, l1;
            split_bf16(v0, h0, l0);
            split_bf16(v1, h1, l1);
            const size_t idx = tok * DMODEL + (size_t)h * DHEAD + on * 8 + tig * 2;
            *(__nv_bfloat162*)(ohi + idx) = __nv_bfloat162(h0, h1);
            *(__nv_bfloat162*)(olo + idx) = __nv_bfloat162(l0, l1);
        }
    }
}

// ---------------- SiLU(gate) * up -> bf16 hi/lo (fused split) ----------------
__global__ __launch_bounds__(256) void silu_mul_kernel(
    const float* __restrict__ gu, __nv_bfloat16* __restrict__ hi, __nv_bfloat16* __restrict__ lo)
{
    const int idx = blockIdx.x * 256 + threadIdx.x;
    const int m = idx / (DFF / 4);
    const int c4 = (idx - m * (DFF / 4)) << 2;
    const size_t rb = (size_t)m * (2 * DFF);
    float4 g = *(const float4*)(gu + rb + c4);
    float4 u = *(const float4*)(gu + rb + DFF + c4);
    float r0 = g.x / (1.f + __expf(-g.x)) * u.x;
    float r1 = g.y / (1.f + __expf(-g.y)) * u.y;
    float r2 = g.z / (1.f + __expf(-g.z)) * u.z;
    float r3 = g.w / (1.f + __expf(-g.w)) * u.w;
    __nv_bfloat16 h0, l0, h1, l1, h2, l2, h3, l3;
    split_bf16(r0, h0, l0); split_bf16(r1, h1, l1);
    split_bf16(r2, h2, l2); split_bf16(r3, h3, l3);
    const size_t oidx = (size_t)m * DFF + c4;
    *(__nv_bfloat162*)(hi + oidx)     = __nv_bfloat162(h0, h1);
    *(__nv_bfloat162*)(hi + oidx + 2) = __nv_bfloat162(h2, h3);
    *(__nv_bfloat162*)(lo + oidx)     = __nv_bfloat162(l0, l1);
    *(__nv_bfloat162*)(lo + oidx + 2) = __nv_bfloat162(l2, l3);
}

// ---------------- launch ----------------
extern "C" void kernel_launch(void* const* d_in, const int* in_sizes, int n_in,
                              void* d_out, int out_size)
{
    const float* hs    = (const float*)d_in[0];
    const int*   pos   = (const int*)  d_in[1];
    const float* ln1w  = (const float*)d_in[2];
    const float* wqkv  = (const float*)d_in[3];
    const float* bqkv  = (const float*)d_in[4];
    const float* wo    = (const float*)d_in[5];
    const float* ln2w  = (const float*)d_in[6];
    const float* wgu   = (const float*)d_in[7];
    const float* wdown = (const float*)d_in[8];
    float* out = (float*)d_out;

    float *qkv, *hidden, *gu;
    __nv_bfloat16 *ahi, *alo, *bhi, *blo;
    cudaGetSymbolAddress((void**)&qkv,    g_qkv);
    cudaGetSymbolAddress((void**)&hidden, g_hidden);
    cudaGetSymbolAddress((void**)&gu,     g_gu);
    cudaGetSymbolAddress((void**)&ahi,    g_ahi);
    cudaGetSymbolAddress((void**)&alo,    g_alo);
    cudaGetSymbolAddress((void**)&bhi,    g_bhi);
    cudaGetSymbolAddress((void**)&blo,    g_blo);

    cudaFuncSetAttribute(attn_kernel, cudaFuncAttributeMaxDynamicSharedMemorySize, ATTN_SMEM);
    cudaFuncSetAttribute(mma_gemm_kernel, cudaFuncAttributeMaxDynamicSharedMemorySize, GSMEM);

    // 1. x = rmsnorm(hs) -> ahi/alo
    rmsnorm_kernel<<<TOKENS, 256>>>(hs, ln1w, ahi, alo);
    // 2. qkv = x @ w_qkv + b
    wsplit_kernel<<<dim3(QKVDIM / 32, DMODEL / 32), 256>>>(wqkv, bhi, blo, DMODEL, QKVDIM);
    mma_gemm_kernel<<<(TOKENS / 128) * (QKVDIM / 128), 256, GSMEM>>>(
        TOKENS, QKVDIM, DMODEL, ahi, alo, bhi, blo, qkv, bqkv, nullptr);
    // 3. rope (in place)
    rope_kernel<<<(TOKENS * NHEADS * 64) / 256, 256>>>(qkv, pos);
    // 4. attention -> ahi/alo
    attn_kernel<<<dim3(SEQ / 128, NHEADS, NBATCH), 256, ATTN_SMEM>>>(qkv, ahi, alo);
    // 5. hidden = hs + attnout @ w_o
    wsplit_kernel<<<dim3(DMODEL / 32, DMODEL / 32), 256>>>(wo, bhi, blo, DMODEL, DMODEL);
    mma_gemm_kernel<<<(TOKENS / 128) * (DMODEL / 128), 256, GSMEM>>>(
        TOKENS, DMODEL, DMODEL, ahi, alo, bhi, blo, hidden, nullptr, hs);
    // 6. x = rmsnorm(hidden) -> ahi/alo
    rmsnorm_kernel<<<TOKENS, 256>>>(hidden, ln2w, ahi, alo);
    // 7. gu = x @ w_gate_up
    wsplit_kernel<<<dim3((2 * DFF) / 32, DMODEL / 32), 256>>>(wgu, bhi, blo, DMODEL, 2 * DFF);
    mma_gemm_kernel<<<(TOKENS / 128) * ((2 * DFF) / 128), 256, GSMEM>>>(
        TOKENS, 2 * DFF, DMODEL, ahi, alo, bhi, blo, gu, nullptr, nullptr);
    // 8. mid = silu(gate)*up -> ahi/alo
    silu_mul_kernel<<<(TOKENS * (DFF / 4)) / 256, 256>>>(gu, ahi, alo);
    // 9. out = hidden + mid @ w_down
    wsplit_kernel<<<dim3(DMODEL / 32, DFF / 32), 256>>>(wdown, bhi, blo, DFF, DMODEL);
    mma_gemm_kernel<<<(TOKENS / 128) * (DMODEL / 128), 256, GSMEM>>>(
        TOKENS, DMODEL, DFF, ahi, alo, bhi, blo, out, nullptr, hidden);
}

// round 17
// speedup vs baseline: 1.1855x; 1.0104x over previous
#include <cuda_runtime.h>
#include <cuda_bf16.h>
#include <cstdint>
#include <math.h>

#define TOKENS 4096
#define DMODEL 4096
#define SEQ    2048
#define NBATCH 2
#define NHEADS 32
#define DHEAD  128
#define DFF    11008
#define QKVDIM (3*DMODEL)

// ---------------- scratch (device globals: allocation-free) ----------------
__device__ float g_qkv    [(size_t)TOKENS * QKVDIM];
__device__ float g_hidden [(size_t)TOKENS * DMODEL];
__device__ float g_gu     [(size_t)TOKENS * 2 * DFF];
__device__ __nv_bfloat16 g_ahi[(size_t)TOKENS * DFF];
__device__ __nv_bfloat16 g_alo[(size_t)TOKENS * DFF];
// dedicated per-weight split buffers (enable stream-overlapped wsplit)
__device__ __nv_bfloat16 g_bqkv_h[(size_t)QKVDIM * DMODEL];
__device__ __nv_bfloat16 g_bqkv_l[(size_t)QKVDIM * DMODEL];
__device__ __nv_bfloat16 g_bwo_h [(size_t)DMODEL * DMODEL];
__device__ __nv_bfloat16 g_bwo_l [(size_t)DMODEL * DMODEL];
__device__ __nv_bfloat16 g_bgu_h [(size_t)(2*DFF) * DMODEL];
__device__ __nv_bfloat16 g_bgu_l [(size_t)(2*DFF) * DMODEL];
__device__ __nv_bfloat16 g_bdn_h [(size_t)DMODEL * DFF];
__device__ __nv_bfloat16 g_bdn_l [(size_t)DMODEL * DFF];

// ================= helpers =================
__device__ __forceinline__ uint32_t smem_u32(const void* p) {
    uint32_t a;
    asm("{ .reg .u64 t; cvta.to.shared.u64 t, %1; cvt.u32.u64 %0, t; }" : "=r"(a) : "l"(p));
    return a;
}
#define CP_ASYNC16(s, g) asm volatile("cp.async.cg.shared.global [%0], [%1], 16;" :: "r"(s), "l"(g))
#define CP_COMMIT() asm volatile("cp.async.commit_group;" ::: "memory")
#define CP_WAIT0()  asm volatile("cp.async.wait_group 0;" ::: "memory")
#define CP_WAIT1()  asm volatile("cp.async.wait_group 1;" ::: "memory")

__device__ __forceinline__ void ldsm_x4(uint32_t* r, uint32_t addr) {
    asm volatile("ldmatrix.sync.aligned.m8n8.x4.shared.b16 {%0,%1,%2,%3}, [%4];"
        : "=r"(r[0]), "=r"(r[1]), "=r"(r[2]), "=r"(r[3]) : "r"(addr));
}
__device__ __forceinline__ void ldsm_x2(uint32_t* r, uint32_t addr) {
    asm volatile("ldmatrix.sync.aligned.m8n8.x2.shared.b16 {%0,%1}, [%2];"
        : "=r"(r[0]), "=r"(r[1]) : "r"(addr));
}
__device__ __forceinline__ void mma16816(float* c, const uint32_t* a, const uint32_t* b) {
    asm volatile(
        "mma.sync.aligned.m16n8k16.row.col.f32.bf16.bf16.f32 "
        "{%0,%1,%2,%3}, {%4,%5,%6,%7}, {%8,%9}, {%0,%1,%2,%3};"
        : "+f"(c[0]), "+f"(c[1]), "+f"(c[2]), "+f"(c[3])
        : "r"(a[0]), "r"(a[1]), "r"(a[2]), "r"(a[3]), "r"(b[0]), "r"(b[1]));
}
__device__ __forceinline__ void split_bf16(float v, __nv_bfloat16& h, __nv_bfloat16& l) {
    h = __float2bfloat16(v);
    l = __float2bfloat16(v - __bfloat162float(h));
}

// ================= HMMA GEMM (bf16 split, fp32 acc) — R8 mainloop (frozen) =================
#define LDAB   40
#define TILEB  (128 * LDAB * 2)
#define OFF_AH 0
#define OFF_AL TILEB
#define OFF_BH (2*TILEB)
#define OFF_BL (3*TILEB)
#define BUFB   (4*TILEB)
#define GSMEM  (2*BUFB)
#define RASTG  8

__device__ __forceinline__ void g2s_tile(uint32_t dst, const __nv_bfloat16* src,
                                         int row0, int K, int k0, int tid)
{
    #pragma unroll
    for (int it = 0; it < 2; it++) {
        int idx = tid + it * 256;
        int r = idx >> 2, c8 = (idx & 3) << 3;
        CP_ASYNC16(dst + r * 80 + (c8 << 1),
                   (const char*)(src + (size_t)(row0 + r) * K + k0 + c8));
    }
}

__global__ __launch_bounds__(256, 2) void mma_gemm_kernel(
    int M, int N, int K,
    const __nv_bfloat16* __restrict__ Ah, const __nv_bfloat16* __restrict__ Al,
    const __nv_bfloat16* __restrict__ Bh, const __nv_bfloat16* __restrict__ Bl,
    float* __restrict__ C, const float* __restrict__ bias, const float* __restrict__ res)
{
    extern __shared__ char smem[];
    const uint32_t sb = smem_u32(smem);
    const int tid = threadIdx.x;
    const int wid = tid >> 5, lane = tid & 31;
    const int g = lane >> 2, tig = lane & 3;
    const int wm = wid & 3, wn = wid >> 2;

    const int NB = N >> 7, MB = M >> 7;
    const int bid = blockIdx.x;
    const int per_group = RASTG * NB;
    const int group = bid / per_group;
    const int first_m = group * RASTG;
    const int gsz = min(RASTG, MB - first_m);
    const int rem = bid - group * per_group;
    const int bm = (first_m + rem % gsz) << 7;
    const int bn = (rem / gsz) << 7;

    const int rsel = lane & 15;
    const int kh   = lane >> 4;
    const int brow = lane & 7;
    const int bkh  = (lane >> 3) & 1;

    float acc[2][8][4];
    #pragma unroll
    for (int mt = 0; mt < 2; mt++)
        #pragma unroll
        for (int nt = 0; nt < 8; nt++)
            #pragma unroll
            for (int e = 0; e < 4; e++) acc[mt][nt][e] = 0.f;

    const int NC = K >> 5;
    g2s_tile(sb + OFF_AH, Ah, bm, K, 0, tid);
    g2s_tile(sb + OFF_AL, Al, bm, K, 0, tid);
    g2s_tile(sb + OFF_BH, Bh, bn, K, 0, tid);
    g2s_tile(sb + OFF_BL, Bl, bn, K, 0, tid);
    CP_COMMIT();

    for (int ck = 0; ck < NC; ck++) {
        if (ck + 1 < NC) {
            const uint32_t nb = sb + (uint32_t)((ck + 1) & 1) * BUFB;
            const int k1 = (ck + 1) << 5;
            g2s_tile(nb + OFF_AH, Ah, bm, K, k1, tid);
            g2s_tile(nb + OFF_AL, Al, bm, K, k1, tid);
            g2s_tile(nb + OFF_BH, Bh, bn, K, k1, tid);
            g2s_tile(nb + OFF_BL, Bl, bn, K, k1, tid);
            CP_COMMIT();
            CP_WAIT1();
        } else {
            CP_WAIT0();
        }
        __syncthreads();

        const uint32_t bb = sb + (uint32_t)(ck & 1) * BUFB;
        #pragma unroll
        for (int ks = 0; ks < 2; ks++) {
            uint32_t ahf[2][4], alf[2][4];
            #pragma unroll
            for (int mt = 0; mt < 2; mt++) {
                const uint32_t ao = (uint32_t)((wm * 32 + mt * 16 + rsel) * 80
                                               + ((ks << 4) + kh * 8) * 2);
                ldsm_x4(ahf[mt], bb + OFF_AH + ao);
                ldsm_x4(alf[mt], bb + OFF_AL + ao);
            }
            #pragma unroll
            for (int nt = 0; nt < 8; nt++) {
                const uint32_t bo = (uint32_t)((wn * 64 + nt * 8 + brow) * 80
                                               + ((ks << 4) + bkh * 8) * 2);
                uint32_t bh[2], bl[2];
                ldsm_x2(bh, bb + OFF_BH + bo);
                ldsm_x2(bl, bb + OFF_BL + bo);
                #pragma unroll
                for (int mt = 0; mt < 2; mt++) {
                    mma16816(acc[mt][nt], ahf[mt], bh);
                    mma16816(acc[mt][nt], alf[mt], bh);
                    mma16816(acc[mt][nt], ahf[mt], bl);
                }
            }
        }
        __syncthreads();
    }

    #pragma unroll
    for (int nt = 0; nt < 8; nt++) {
        const int c = bn + wn * 64 + nt * 8 + (tig << 1);
        float bx = 0.f, by = 0.f;
        if (bias) { bx = bias[c]; by = bias[c + 1]; }
        #pragma unroll
        for (int mt = 0; mt < 2; mt++) {
            const int r0 = bm + wm * 32 + mt * 16 + g;
            float2 v0 = make_float2(acc[mt][nt][0] + bx, acc[mt][nt][1] + by);
            float2 v1 = make_float2(acc[mt][nt][2] + bx, acc[mt][nt][3] + by);
            size_t g0 = (size_t)r0 * N + c;
            size_t g1 = (size_t)(r0 + 8) * N + c;
            if (res) {
                float2 r0v = *(const float2*)(res + g0);
                float2 r1v = *(const float2*)(res + g1);
                v0.x += r0v.x; v0.y += r0v.y; v1.x += r1v.x; v1.y += r1v.y;
            }
            *(float2*)(C + g0) = v0;
            *(float2*)(C + g1) = v1;
        }
    }
}

// ---------------- split + transpose fp32 W[K,N] -> bf16 hi/lo [N,K] ----------------
__global__ __launch_bounds__(256) void wsplit_kernel(
    const float* __restrict__ W, __nv_bfloat16* __restrict__ hi, __nv_bfloat16* __restrict__ lo,
    int K, int N)
{
    __shared__ float t[32][33];
    const int n0 = blockIdx.x * 32, k0 = blockIdx.y * 32;
    const int tx = threadIdx.x & 31, ty = threadIdx.x >> 5;
    #pragma unroll
    for (int i = ty; i < 32; i += 8)
        t[i][tx] = W[(size_t)(k0 + i) * N + n0 + tx];
    __syncthreads();
    #pragma unroll
    for (int i = ty; i < 32; i += 8) {
        float v = t[tx][i];
        __nv_bfloat16 h, l;
        split_bf16(v, h, l);
        size_t o = (size_t)(n0 + i) * K + k0 + tx;
        hi[o] = h; lo[o] = l;
    }
}

// ---------------- RMSNorm -> bf16 hi/lo (fused split) ----------------
__global__ __launch_bounds__(256) void rmsnorm_kernel(
    const float* __restrict__ x, const float* __restrict__ w,
    __nv_bfloat16* __restrict__ hi, __nv_bfloat16* __restrict__ lo)
{
    const int row = blockIdx.x;
    const int t = threadIdx.x;
    const float4* xr = (const float4*)(x + (size_t)row * DMODEL);
    float4 buf[4];
    float ss = 0.f;
    #pragma unroll
    for (int i = 0; i < 4; i++) {
        float4 v = xr[t + i * 256];
        buf[i] = v;
        ss += v.x*v.x + v.y*v.y + v.z*v.z + v.w*v.w;
    }
    __shared__ float red[8];
    #pragma unroll
    for (int o = 16; o > 0; o >>= 1) ss += __shfl_xor_sync(0xffffffffu, ss, o);
    if ((t & 31) == 0) red[t >> 5] = ss;
    __syncthreads();
    if (t < 32) {
        float v = (t < 8) ? red[t] : 0.f;
        #pragma unroll
        for (int o = 4; o > 0; o >>= 1) v += __shfl_xor_sync(0xffffffffu, v, o);
        if (t == 0) red[0] = v;
    }
    __syncthreads();
    const float inv = rsqrtf(red[0] * (1.f / DMODEL) + 1e-6f);
    const float4* wr = (const float4*)w;
    #pragma unroll
    for (int i = 0; i < 4; i++) {
        float4 v = buf[i];
        float4 ww = wr[t + i * 256];
        float f0 = v.x * inv * ww.x, f1 = v.y * inv * ww.y;
        float f2 = v.z * inv * ww.z, f3 = v.w * inv * ww.w;
        __nv_bfloat16 h0, l0, h1, l1, h2, l2, h3, l3;
        split_bf16(f0, h0, l0); split_bf16(f1, h1, l1);
        split_bf16(f2, h2, l2); split_bf16(f3, h3, l3);
        const size_t idx = (size_t)row * DMODEL + (t + i * 256) * 4;
        *(__nv_bfloat162*)(hi + idx)     = __nv_bfloat162(h0, h1);
        *(__nv_bfloat162*)(hi + idx + 2) = __nv_bfloat162(h2, h3);
        *(__nv_bfloat162*)(lo + idx)     = __nv_bfloat162(l0, l1);
        *(__nv_bfloat162*)(lo + idx + 2) = __nv_bfloat162(l2, l3);
    }
}

// ---------------- RoPE (in place, fp32) ----------------
__global__ __launch_bounds__(256) void rope_kernel(
    float* __restrict__ qkv, const int* __restrict__ pos)
{
    const int idx = blockIdx.x * 256 + threadIdx.x;
    const int i   = idx & 63;
    const int h   = (idx >> 6) & 31;
    const int tkn = idx >> 11;
    const float p = (float)pos[tkn];
    const float inv_freq = 1.f / powf(10000.f, (float)i * (1.f / 64.f));
    float sv, cv;
    sincosf(p * inv_freq, &sv, &cv);
    const size_t base = (size_t)tkn * QKVDIM + (size_t)h * DHEAD + i;
    float q1 = qkv[base], q2 = qkv[base + 64];
    qkv[base]      = q1 * cv - q2 * sv;
    qkv[base + 64] = q2 * cv + q1 * sv;
    float k1 = qkv[base + DMODEL], k2 = qkv[base + DMODEL + 64];
    qkv[base + DMODEL]      = k1 * cv - k2 * sv;
    qkv[base + DMODEL + 64] = k2 * cv + k1 * sv;
}

// ================= Flash attention (R16: 3-term S, 2-term PV) =================
#define AQS 136
#define AVS 72
#define ATTN_ELEMS (2*(128*AQS) + 2*(64*AQS) + (128*AVS))
#define ATTN_SMEM  (ATTN_ELEMS * 2)

__global__ __launch_bounds__(256) void attn_kernel(
    const float* __restrict__ qkv,
    __nv_bfloat16* __restrict__ ohi, __nv_bfloat16* __restrict__ olo)
{
    extern __shared__ __nv_bfloat16 smb[];
    __nv_bfloat16* Qh = smb;
    __nv_bfloat16* Ql = Qh + 128 * AQS;
    __nv_bfloat16* Kh = Ql + 128 * AQS;
    __nv_bfloat16* Kl = Kh + 64 * AQS;
    __nv_bfloat16* Vh = Kl + 64 * AQS;
    const uint32_t sQh = smem_u32(Qh), sQl = smem_u32(Ql);
    const uint32_t sKh = smem_u32(Kh), sKl = smem_u32(Kl);
    const uint32_t sVh = smem_u32(Vh);

    const int q0 = (gridDim.x - 1 - blockIdx.x) * 128;
    const int h  = blockIdx.y;
    const int b  = blockIdx.z;
    const int tid = threadIdx.x;
    const int wid = tid >> 5, lane = tid & 31;
    const int g = lane >> 2, tig = lane & 3;
    const int rsel = lane & 15, kh = lane >> 4;
    const int brow = lane & 7, bkh = (lane >> 3) & 1;
    const float scale = 0.08838834764831845f;

    const size_t base = (size_t)(b * SEQ) * QKVDIM + (size_t)h * DHEAD;
    const int lr0 = tid >> 5, lc4 = (tid & 31) << 2;

    for (int idx = tid; idx < 128 * 32; idx += 256) {
        const int r = idx >> 5, c4 = (idx & 31) << 2;
        float4 v = *(const float4*)(qkv + base + (size_t)(q0 + r) * QKVDIM + c4);
        __nv_bfloat16 h0, l0, h1, l1, h2, l2, h3, l3;
        split_bf16(v.x, h0, l0); split_bf16(v.y, h1, l1);
        split_bf16(v.z, h2, l2); split_bf16(v.w, h3, l3);
        __nv_bfloat162* ph = (__nv_bfloat162*)(Qh + r * AQS + c4);
        __nv_bfloat162* pl = (__nv_bfloat162*)(Ql + r * AQS + c4);
        ph[0] = __nv_bfloat162(h0, h1); ph[1] = __nv_bfloat162(h2, h3);
        pl[0] = __nv_bfloat162(l0, l1); pl[1] = __nv_bfloat162(l2, l3);
    }

    float o[16][4];
    #pragma unroll
    for (int on = 0; on < 16; on++)
        #pragma unroll
        for (int e = 0; e < 4; e++) o[on][e] = 0.f;
    float m_i[2] = {-1e30f, -1e30f}, l_i[2] = {0.f, 0.f};

    const int ntk = q0 / 64 + 2;
    float4 kreg[8], vreg[8];

    #pragma unroll
    for (int i = 0; i < 8; i++)
        kreg[i] = *(const float4*)(qkv + base + (size_t)(lr0 + i * 8) * QKVDIM + DMODEL + lc4);

    for (int kt = 0; kt < ntk; kt++) {
        const int k0 = kt * 64;
        __syncthreads();

        #pragma unroll
        for (int i = 0; i < 8; i++) {
            const int r = lr0 + i * 8;
            float4 kv = kreg[i];
            __nv_bfloat16 h0, l0, h1, l1, h2, l2, h3, l3;
            split_bf16(kv.x, h0, l0); split_bf16(kv.y, h1, l1);
            split_bf16(kv.z, h2, l2); split_bf16(kv.w, h3, l3);
            __nv_bfloat162* ph = (__nv_bfloat162*)(Kh + r * AQS + lc4);
            __nv_bfloat162* pl = (__nv_bfloat162*)(Kl + r * AQS + lc4);
            ph[0] = __nv_bfloat162(h0, h1); ph[1] = __nv_bfloat162(h2, h3);
            pl[0] = __nv_bfloat162(l0, l1); pl[1] = __nv_bfloat162(l2, l3);
        }
        #pragma unroll
        for (int i = 0; i < 8; i++)
            vreg[i] = *(const float4*)(qkv + base + (size_t)(k0 + lr0 + i * 8) * QKVDIM
                                       + 2 * DMODEL + lc4);
        __syncthreads();

        if (kt + 1 < ntk) {
            const int k1 = (kt + 1) * 64;
            #pragma unroll
            for (int i = 0; i < 8; i++)
                kreg[i] = *(const float4*)(qkv + base + (size_t)(k1 + lr0 + i * 8) * QKVDIM
                                           + DMODEL + lc4);
        }

        float s[8][4];
        #pragma unroll
        for (int nt = 0; nt < 8; nt++)
            #pragma unroll
            for (int e = 0; e < 4; e++) s[nt][e] = 0.f;
        #pragma unroll
        for (int ks = 0; ks < 8; ks++) {
            uint32_t ah[4], al[4];
            const uint32_t qo = (uint32_t)(((wid * 16 + rsel) * AQS + (ks << 4) + kh * 8) * 2);
            ldsm_x4(ah, sQh + qo);
            ldsm_x4(al, sQl + qo);
            #pragma unroll
            for (int nt = 0; nt < 8; nt++) {
                const uint32_t ko = (uint32_t)(((nt * 8 + brow) * AQS + (ks << 4) + bkh * 8) * 2);
                uint32_t bh[2], bl[2];
                ldsm_x2(bh, sKh + ko);
                ldsm_x2(bl, sKl + ko);
                mma16816(s[nt], ah, bh);
                mma16816(s[nt], al, bh);
                mma16816(s[nt], ah, bl);
            }
        }

        const bool need_mask = (kt >= ntk - 2);
        #pragma unroll
        for (int rr = 0; rr < 2; rr++) {
            const int qrow = q0 + wid * 16 + g + rr * 8;
            float rmax = -1e30f;
            #pragma unroll
            for (int nt = 0; nt < 8; nt++) {
                #pragma unroll
                for (int j = 0; j < 2; j++) {
                    float v = s[nt][rr * 2 + j] * scale;
                    if (need_mask && (k0 + nt * 8 + tig * 2 + j > qrow)) v = -1e30f;
                    s[nt][rr * 2 + j] = v;
                    rmax = fmaxf(rmax, v);
                }
            }
            rmax = fmaxf(rmax, __shfl_xor_sync(0xffffffffu, rmax, 1));
            rmax = fmaxf(rmax, __shfl_xor_sync(0xffffffffu, rmax, 2));
            const float mnew = fmaxf(m_i[rr], rmax);
            const float alpha = __expf(m_i[rr] - mnew);
            m_i[rr] = mnew;
            float rsum = 0.f;
            #pragma unroll
            for (int nt = 0; nt < 8; nt++) {
                #pragma unroll
                for (int j = 0; j < 2; j++) {
                    float p = __expf(s[nt][rr * 2 + j] - mnew);
                    s[nt][rr * 2 + j] = p;
                    rsum += p;
                }
            }
            rsum += __shfl_xor_sync(0xffffffffu, rsum, 1);
            rsum += __shfl_xor_sync(0xffffffffu, rsum, 2);
            l_i[rr] = l_i[rr] * alpha + rsum;
            #pragma unroll
            for (int on = 0; on < 16; on++) {
                o[on][rr * 2]     *= alpha;
                o[on][rr * 2 + 1] *= alpha;
            }
        }

        #pragma unroll
        for (int i = 0; i < 8; i++) {
            const int r = lr0 + i * 8;
            float4 vv = vreg[i];
            float vf[4] = {vv.x, vv.y, vv.z, vv.w};
            #pragma unroll
            for (int j = 0; j < 4; j++)
                Vh[(lc4 + j) * AVS + r] = __float2bfloat16(vf[j]);
        }
        __syncthreads();

        #pragma unroll
        for (int ks2 = 0; ks2 < 4; ks2++) {
            uint32_t pah[4], pal[4];
            #pragma unroll
            for (int half = 0; half < 2; half++) {
                const int nt = 2 * ks2 + half;
                #pragma unroll
                for (int rr = 0; rr < 2; rr++) {
                    float p0 = s[nt][rr * 2], p1 = s[nt][rr * 2 + 1];
                    __nv_bfloat16 h0 = __float2bfloat16(p0);
                    __nv_bfloat16 h1 = __float2bfloat16(p1);
                    __nv_bfloat162 hh = __nv_bfloat162(h0, h1);
                    pah[half * 2 + rr] = *(uint32_t*)&hh;
                    __nv_bfloat162 ll = __nv_bfloat162(
                        __float2bfloat16(p0 - __bfloat162float(h0)),
                        __float2bfloat16(p1 - __bfloat162float(h1)));
                    pal[half * 2 + rr] = *(uint32_t*)&ll;
                }
            }
            #pragma unroll
            for (int on = 0; on < 16; on++) {
                const uint32_t vo = (uint32_t)(((on * 8 + brow) * AVS + (ks2 << 4) + bkh * 8) * 2);
                uint32_t bh[2];
                ldsm_x2(bh, sVh + vo);
                mma16816(o[on], pah, bh);
                mma16816(o[on], pal, bh);
            }
        }
    }

    #pragma unroll
    for (int rr = 0; rr < 2; rr++) {
        const float inv = 1.f / l_i[rr];
        const size_t tok = (size_t)(b * SEQ + q0 + wid * 16 + g + rr * 8);
        #pragma unroll
        for (int on = 0; on < 16; on++) {
            const float v0 = o[on][rr * 2] * inv;
            const float v1 = o[on][rr * 2 + 1] * inv;
            __nv_bfloat16 h0, l0, h1, l1;
            split_bf16(v0, h0, l0);
            split_bf16(v1, h1, l1);
            const size_t idx = tok * DMODEL + (size_t)h * DHEAD + on * 8 + tig * 2;
            *(__nv_bfloat162*)(ohi + idx) = __nv_bfloat162(h0, h1);
            *(__nv_bfloat162*)(olo + idx) = __nv_bfloat162(l0, l1);
        }
    }
}

// ---------------- SiLU(gate) * up -> bf16 hi/lo (fused split) ----------------
__global__ __launch_bounds__(256) void silu_mul_kernel(
    const float* __restrict__ gu, __nv_bfloat16* __restrict__ hi, __nv_bfloat16* __restrict__ lo)
{
    const int idx = blockIdx.x * 256 + threadIdx.x;
    const int m = idx / (DFF / 4);
    const int c4 = (idx - m * (DFF / 4)) << 2;
    const size_t rb = (size_t)m * (2 * DFF);
    float4 g = *(const float4*)(gu + rb + c4);
    float4 u = *(const float4*)(gu + rb + DFF + c4);
    float r0 = g.x / (1.f + __expf(-g.x)) * u.x;
    float r1 = g.y / (1.f + __expf(-g.y)) * u.y;
    float r2 = g.z / (1.f + __expf(-g.z)) * u.z;
    float r3 = g.w / (1.f + __expf(-g.w)) * u.w;
    __nv_bfloat16 h0, l0, h1, l1, h2, l2, h3, l3;
    split_bf16(r0, h0, l0); split_bf16(r1, h1, l1);
    split_bf16(r2, h2, l2); split_bf16(r3, h3, l3);
    const size_t oidx = (size_t)m * DFF + c4;
    *(__nv_bfloat162*)(hi + oidx)     = __nv_bfloat162(h0, h1);
    *(__nv_bfloat162*)(hi + oidx + 2) = __nv_bfloat162(h2, h3);
    *(__nv_bfloat162*)(lo + oidx)     = __nv_bfloat162(l0, l1);
    *(__nv_bfloat162*)(lo + oidx + 2) = __nv_bfloat162(l2, l3);
}

// ---------------- launch ----------------
extern "C" void kernel_launch(void* const* d_in, const int* in_sizes, int n_in,
                              void* d_out, int out_size)
{
    const float* hs    = (const float*)d_in[0];
    const int*   pos   = (const int*)  d_in[1];
    const float* ln1w  = (const float*)d_in[2];
    const float* wqkv  = (const float*)d_in[3];
    const float* bqkv  = (const float*)d_in[4];
    const float* wo    = (const float*)d_in[5];
    const float* ln2w  = (const float*)d_in[6];
    const float* wgu   = (const float*)d_in[7];
    const float* wdown = (const float*)d_in[8];
    float* out = (float*)d_out;

    float *qkv, *hidden, *gu;
    __nv_bfloat16 *ahi, *alo;
    __nv_bfloat16 *bqh, *bql, *bwh, *bwl, *bgh, *bgl, *bdh, *bdl;
    cudaGetSymbolAddress((void**)&qkv,    g_qkv);
    cudaGetSymbolAddress((void**)&hidden, g_hidden);
    cudaGetSymbolAddress((void**)&gu,     g_gu);
    cudaGetSymbolAddress((void**)&ahi,    g_ahi);
    cudaGetSymbolAddress((void**)&alo,    g_alo);
    cudaGetSymbolAddress((void**)&bqh,    g_bqkv_h);
    cudaGetSymbolAddress((void**)&bql,    g_bqkv_l);
    cudaGetSymbolAddress((void**)&bwh,    g_bwo_h);
    cudaGetSymbolAddress((void**)&bwl,    g_bwo_l);
    cudaGetSymbolAddress((void**)&bgh,    g_bgu_h);
    cudaGetSymbolAddress((void**)&bgl,    g_bgu_l);
    cudaGetSymbolAddress((void**)&bdh,    g_bdn_h);
    cudaGetSymbolAddress((void**)&bdl,    g_bdn_l);

    cudaFuncSetAttribute(attn_kernel, cudaFuncAttributeMaxDynamicSharedMemorySize, ATTN_SMEM);
    cudaFuncSetAttribute(mma_gemm_kernel, cudaFuncAttributeMaxDynamicSharedMemorySize, GSMEM);

    // fork a side stream for the weight splits (independent of activations)
    cudaStream_t ws;
    cudaStreamCreateWithFlags(&ws, cudaStreamNonBlocking);
    cudaEvent_t e0, e1, e2, e3, e4;
    cudaEventCreateWithFlags(&e0, cudaEventDisableTiming);
    cudaEventCreateWithFlags(&e1, cudaEventDisableTiming);
    cudaEventCreateWithFlags(&e2, cudaEventDisableTiming);
    cudaEventCreateWithFlags(&e3, cudaEventDisableTiming);
    cudaEventCreateWithFlags(&e4, cudaEventDisableTiming);

    cudaEventRecord(e0, 0);
    cudaStreamWaitEvent(ws, e0, 0);
    wsplit_kernel<<<dim3(QKVDIM / 32, DMODEL / 32), 256, 0, ws>>>(wqkv, bqh, bql, DMODEL, QKVDIM);
    cudaEventRecord(e1, ws);
    wsplit_kernel<<<dim3(DMODEL / 32, DMODEL / 32), 256, 0, ws>>>(wo, bwh, bwl, DMODEL, DMODEL);
    cudaEventRecord(e2, ws);
    wsplit_kernel<<<dim3((2 * DFF) / 32, DMODEL / 32), 256, 0, ws>>>(wgu, bgh, bgl, DMODEL, 2 * DFF);
    cudaEventRecord(e3, ws);
    wsplit_kernel<<<dim3(DMODEL / 32, DFF / 32), 256, 0, ws>>>(wdown, bdh, bdl, DFF, DMODEL);
    cudaEventRecord(e4, ws);

    // main stream
    // 1. x = rmsnorm(hs) -> ahi/alo
    rmsnorm_kernel<<<TOKENS, 256>>>(hs, ln1w, ahi, alo);
    // 2. qkv = x @ w_qkv + b
    cudaStreamWaitEvent(0, e1, 0);
    mma_gemm_kernel<<<(TOKENS / 128) * (QKVDIM / 128), 256, GSMEM>>>(
        TOKENS, QKVDIM, DMODEL, ahi, alo, bqh, bql, qkv, bqkv, nullptr);
    // 3. rope (in place)
    rope_kernel<<<(TOKENS * NHEADS * 64) / 256, 256>>>(qkv, pos);
    // 4. attention -> ahi/alo
    attn_kernel<<<dim3(SEQ / 128, NHEADS, NBATCH), 256, ATTN_SMEM>>>(qkv, ahi, alo);
    // 5. hidden = hs + attnout @ w_o
    cudaStreamWaitEvent(0, e2, 0);
    mma_gemm_kernel<<<(TOKENS / 128) * (DMODEL / 128), 256, GSMEM>>>(
        TOKENS, DMODEL, DMODEL, ahi, alo, bwh, bwl, hidden, nullptr, hs);
    // 6. x = rmsnorm(hidden) -> ahi/alo
    rmsnorm_kernel<<<TOKENS, 256>>>(hidden, ln2w, ahi, alo);
    // 7. gu = x @ w_gate_up
    cudaStreamWaitEvent(0, e3, 0);
    mma_gemm_kernel<<<(TOKENS / 128) * ((2 * DFF) / 128), 256, GSMEM>>>(
        TOKENS, 2 * DFF, DMODEL, ahi, alo, bgh, bgl, gu, nullptr, nullptr);
    // 8. mid = silu(gate)*up -> ahi/alo
    silu_mul_kernel<<<(TOKENS * (DFF / 4)) / 256, 256>>>(gu, ahi, alo);
    // 9. out = hidden + mid @ w_down
    cudaStreamWaitEvent(0, e4, 0);
    mma_gemm_kernel<<<(TOKENS / 128) * (DMODEL / 128), 256, GSMEM>>>(
        TOKENS, DMODEL, DFF, ahi, alo, bdh, bdl, out, nullptr, hidden);

    cudaEventDestroy(e0); cudaEventDestroy(e1); cudaEventDestroy(e2);
    cudaEventDestroy(e3); cudaEventDestroy(e4);
    cudaStreamDestroy(ws);
}